// round 9
// baseline (speedup 1.0000x reference)
#include <cuda_runtime.h>
#include <cuda_bf16.h>
#include <cstdint>

#define NN      61440        // nodes = 2048*30
#define EE      245760       // edges = 4*NN
#define BB      2048         // graphs
#define NATOMS  30
#define FL      64           // FEATURE_LEN
#define DD      256          // DIM_ATOM == DIM_GRAPH
#define SSIDE   2            // S
#define KNEI    32

// ---------------- device scratch (no runtime allocation allowed) ------------
__device__ float    g_norm_src[NN];
__device__ float    g_norm_dst[NN];
__device__ unsigned g_cnt[NN];          // in-degree histogram
__device__ unsigned g_rowptr[NN + 1];   // CSR row offsets by dst
__device__ unsigned g_fill[NN];         // placement cursors
__device__ int      g_srcsorted[EE];    // src ids grouped by dst
__device__ float    g_agg1[NN * FL];
__device__ float    g_h1[NN * DD];
__device__ float    g_agg2[NN * DD];
__device__ float    g_h2[NN * DD];
__device__ float    g_item[SSIDE * BB * DD];
__device__ float    g_target[BB * DD];
__device__ float    g_react[BB * DD];
__device__ float    g_normsum;

// ---------------- zero accumulators (agg2 NOT zeroed: gather overwrites) ----
__global__ void k_zero_all() {
    int t = blockIdx.x * blockDim.x + threadIdx.x;   // 3840*256 = 983040
    float4 z = make_float4(0.f, 0.f, 0.f, 0.f);
    ((float4*)g_agg1)[t] = z;                         // NN*FL/4 = 983040 exactly
    if (t < NN / 4) {
        ((float4*)g_norm_src)[t] = z;
        ((uint4*)g_cnt)[t] = make_uint4(0u, 0u, 0u, 0u);
        ((uint4*)g_fill)[t] = make_uint4(0u, 0u, 0u, 0u);
    }
    if (t == 0) g_normsum = 0.f;
}

// ---------------- degrees: float out-deg + int in-deg histogram -------------
__global__ void k_deg(const int* __restrict__ src, const int* __restrict__ dst) {
    int e = blockIdx.x * blockDim.x + threadIdx.x;
    if (e < EE) {
        atomicAdd(&g_norm_src[__ldg(&src[e])], 1.0f);
        atomicAdd(&g_cnt[__ldg(&dst[e])], 1u);
    }
}

__global__ void k_norm() {
    int n = blockIdx.x * blockDim.x + threadIdx.x;
    if (n < NN) {
        g_norm_src[n] = rsqrtf(fmaxf(g_norm_src[n], 1.0f));
        g_norm_dst[n] = rsqrtf(fmaxf((float)g_cnt[n], 1.0f));
    }
}

// ---------------- exclusive scan of g_cnt -> g_rowptr (1 block, 1024 thr) ---
__global__ __launch_bounds__(1024) void k_scan() {
    __shared__ unsigned part[1024];
    int t = threadIdx.x;
    int base = t * 60;                                // 1024*60 = NN exactly
    unsigned s = 0;
#pragma unroll 4
    for (int i = 0; i < 60; i++) s += g_cnt[base + i];
    part[t] = s;
    __syncthreads();
    for (int off = 1; off < 1024; off <<= 1) {        // inclusive Hillis-Steele
        unsigned u = (t >= off) ? part[t - off] : 0u;
        __syncthreads();
        part[t] += u;
        __syncthreads();
    }
    unsigned run = part[t] - s;                       // exclusive offset
#pragma unroll 4
    for (int i = 0; i < 60; i++) {
        g_rowptr[base + i] = run;
        run += g_cnt[base + i];
    }
    if (t == 1023) g_rowptr[NN] = run;                // == EE
}

// ---------------- bin edges by dst ------------------------------------------
__global__ void k_place(const int* __restrict__ src, const int* __restrict__ dst) {
    int e = blockIdx.x * blockDim.x + threadIdx.x;
    if (e < EE) {
        int d = __ldg(&dst[e]);
        unsigned pos = g_rowptr[d] + atomicAdd(&g_fill[d], 1u);
        g_srcsorted[pos] = __ldg(&src[e]);
    }
}

// ---------------- layer-1 sparse scatter (one-hot messages) -----------------
__global__ void k_scatter1(const int* __restrict__ src, const int* __restrict__ dst,
                           const int* __restrict__ feat) {
    int e = blockIdx.x * blockDim.x + threadIdx.x;
    if (e < EE) {
        int s = __ldg(&src[e]), d = __ldg(&dst[e]);
        float ns = g_norm_src[s];
        float* ag = &g_agg1[d * FL];
        int4 f = *(const int4*)&feat[s * 4];
        atomicAdd(&ag[f.x], ns);
        atomicAdd(&ag[f.y], ns);
        atomicAdd(&ag[f.z], ns);
        atomicAdd(&ag[f.w], ns);
    }
}

// ---------------- layer-2 dense aggregation: CSR gather (no atomics) --------
// 64 threads per dst row, float4 per thread; h1 rows stream through L2.
__global__ void k_gather() {
    int t = blockIdx.x * blockDim.x + threadIdx.x;
    int row = t >> 6;
    int c = (t & 63) * 4;
    unsigned beg = g_rowptr[row], end = g_rowptr[row + 1];
    float4 acc = make_float4(0.f, 0.f, 0.f, 0.f);
    for (unsigned j = beg; j < end; j++) {
        int s = g_srcsorted[j];                       // broadcast across group
        float ns = g_norm_src[s];
        float4 v = *(const float4*)&g_h1[(size_t)s * DD + c];
        acc.x += ns * v.x; acc.y += ns * v.y;
        acc.z += ns * v.z; acc.w += ns * v.w;
    }
    *(float4*)&g_agg2[(size_t)row * DD + c] = acc;
}

// ============================================================================
//  mma.sync bf16 3-split GEMM:  out[M,256] = (A*rowscale)[M,K] @ W[K,256] + b
// ============================================================================
#define SMS 36   // smem row stride in bf16 elements (32 + 4 pad)

__device__ __forceinline__ void mma16816(float* c, const uint32_t* a,
                                         const uint32_t* b) {
    asm volatile(
        "mma.sync.aligned.m16n8k16.row.col.f32.bf16.bf16.f32 "
        "{%0,%1,%2,%3}, {%4,%5,%6,%7}, {%8,%9}, {%0,%1,%2,%3};"
        : "+f"(c[0]), "+f"(c[1]), "+f"(c[2]), "+f"(c[3])
        : "r"(a[0]), "r"(a[1]), "r"(a[2]), "r"(a[3]), "r"(b[0]), "r"(b[1]));
}

__global__ __launch_bounds__(256) void k_mgemm(
    const float* __restrict__ A, const float* __restrict__ rowscale,
    const float* __restrict__ W, const float* __restrict__ bias,
    float* __restrict__ out, int K, int relu)
{
    __shared__ __nv_bfloat16 AsH[128 * SMS];
    __shared__ __nv_bfloat16 AsL[128 * SMS];
    __shared__ __nv_bfloat16 BsH[128 * SMS];
    __shared__ __nv_bfloat16 BsL[128 * SMS];

    int tid = threadIdx.x;
    int wid = tid >> 5, lane = tid & 31;
    int warpM = wid & 1, warpN = wid >> 1;     // 2 x 4 warp grid
    int g = lane >> 2, tg = lane & 3;          // mma group / thread-in-group
    int bm = blockIdx.x * 128;
    int bn = blockIdx.y * 128;

    float acc[4][4][4];
#pragma unroll
    for (int mi = 0; mi < 4; mi++)
#pragma unroll
        for (int ni = 0; ni < 4; ni++)
#pragma unroll
            for (int r = 0; r < 4; r++) acc[mi][ni][r] = 0.f;

    int arow = tid >> 1, ahalf = tid & 1;      // A loader: 128 rows x 2 halves
    float rsc = rowscale ? __ldg(&rowscale[bm + arow]) : 1.0f;
    int bk = tid >> 3, bn16 = (tid & 7) * 16;  // B loader: 32 k-rows x 8 n-grp

    for (int kc = 0; kc < K; kc += 32) {
        // ---- A chunk 128x32: split hi/lo ----
        {
            const float* ap = &A[(size_t)(bm + arow) * K + kc + ahalf * 16];
            int base = arow * SMS + ahalf * 16;
#pragma unroll
            for (int i = 0; i < 4; i++) {
                float4 v = *(const float4*)(ap + i * 4);
                v.x *= rsc; v.y *= rsc; v.z *= rsc; v.w *= rsc;
                __nv_bfloat16 hx = __float2bfloat16_rn(v.x);
                __nv_bfloat16 hy = __float2bfloat16_rn(v.y);
                __nv_bfloat16 hz = __float2bfloat16_rn(v.z);
                __nv_bfloat16 hw = __float2bfloat16_rn(v.w);
                __nv_bfloat162 hxy = __halves2bfloat162(hx, hy);
                __nv_bfloat162 hzw = __halves2bfloat162(hz, hw);
                __nv_bfloat162 lxy = __floats2bfloat162_rn(
                    v.x - __bfloat162float(hx), v.y - __bfloat162float(hy));
                __nv_bfloat162 lzw = __floats2bfloat162_rn(
                    v.z - __bfloat162float(hz), v.w - __bfloat162float(hw));
                *(__nv_bfloat162*)&AsH[base + i * 4]     = hxy;
                *(__nv_bfloat162*)&AsH[base + i * 4 + 2] = hzw;
                *(__nv_bfloat162*)&AsL[base + i * 4]     = lxy;
                *(__nv_bfloat162*)&AsL[base + i * 4 + 2] = lzw;
            }
        }
        // ---- B chunk 32x128 -> transposed Bs[n][k], split hi/lo ----
        {
            const float* wp = &W[(size_t)(kc + bk) * 256 + bn + bn16];
#pragma unroll
            for (int j4 = 0; j4 < 4; j4++) {
                float4 v = *(const float4*)(wp + j4 * 4);
                float vv[4] = {v.x, v.y, v.z, v.w};
#pragma unroll
                for (int e2 = 0; e2 < 4; e2++) {
                    int n = bn16 + j4 * 4 + e2;
                    __nv_bfloat16 h = __float2bfloat16_rn(vv[e2]);
                    BsH[n * SMS + bk] = h;
                    BsL[n * SMS + bk] = __float2bfloat16_rn(vv[e2] - __bfloat162float(h));
                }
            }
        }
        __syncthreads();

#pragma unroll
        for (int ks = 0; ks < 32; ks += 16) {
            uint32_t aH[4][4], aL[4][4], bH[4][2], bL[4][2];
#pragma unroll
            for (int mi = 0; mi < 4; mi++) {
                int r0 = (warpM * 64 + mi * 16 + g) * SMS + ks + tg * 2;
                int r1 = r0 + 8 * SMS;
                aH[mi][0] = *(const uint32_t*)&AsH[r0];
                aH[mi][1] = *(const uint32_t*)&AsH[r1];
                aH[mi][2] = *(const uint32_t*)&AsH[r0 + 8];
                aH[mi][3] = *(const uint32_t*)&AsH[r1 + 8];
                aL[mi][0] = *(const uint32_t*)&AsL[r0];
                aL[mi][1] = *(const uint32_t*)&AsL[r1];
                aL[mi][2] = *(const uint32_t*)&AsL[r0 + 8];
                aL[mi][3] = *(const uint32_t*)&AsL[r1 + 8];
            }
#pragma unroll
            for (int ni = 0; ni < 4; ni++) {
                int n0 = (warpN * 32 + ni * 8 + g) * SMS + ks + tg * 2;
                bH[ni][0] = *(const uint32_t*)&BsH[n0];
                bH[ni][1] = *(const uint32_t*)&BsH[n0 + 8];
                bL[ni][0] = *(const uint32_t*)&BsL[n0];
                bL[ni][1] = *(const uint32_t*)&BsL[n0 + 8];
            }
#pragma unroll
            for (int mi = 0; mi < 4; mi++)
#pragma unroll
                for (int ni = 0; ni < 4; ni++) {
                    mma16816(acc[mi][ni], aH[mi], bH[ni]);
                    mma16816(acc[mi][ni], aL[mi], bH[ni]);
                    mma16816(acc[mi][ni], aH[mi], bL[ni]);
                }
        }
        __syncthreads();
    }

    // ---- epilogue: bias (+relu), write fp32 ----
#pragma unroll
    for (int mi = 0; mi < 4; mi++) {
        int row0 = bm + warpM * 64 + mi * 16 + g;
#pragma unroll
        for (int ni = 0; ni < 4; ni++) {
            int col = bn + warpN * 32 + ni * 8 + tg * 2;
            float b0 = __ldg(&bias[col]), b1 = __ldg(&bias[col + 1]);
            float2 v0, v1;
            v0.x = acc[mi][ni][0] + b0; v0.y = acc[mi][ni][1] + b1;
            v1.x = acc[mi][ni][2] + b0; v1.y = acc[mi][ni][3] + b1;
            if (relu) {
                v0.x = fmaxf(v0.x, 0.f); v0.y = fmaxf(v0.y, 0.f);
                v1.x = fmaxf(v1.x, 0.f); v1.y = fmaxf(v1.y, 0.f);
            }
            *(float2*)&out[(size_t)row0 * 256 + col] = v0;
            *(float2*)&out[(size_t)(row0 + 8) * 256 + col] = v1;
        }
    }
}

// ---------------- mean row-norm of h2 ---------------------------------------
__global__ void k_normreduce() {
    int gwarp = (blockIdx.x * blockDim.x + threadIdx.x) >> 5;
    int lane = threadIdx.x & 31;
    float nrm = 0.f;
    {
        const float* row = &g_h2[(size_t)gwarp * DD];
        float ss = 0.f;
#pragma unroll
        for (int i = 0; i < 8; i++) {
            float v = row[lane + i * 32];
            ss += v * v;
        }
#pragma unroll
        for (int o = 16; o > 0; o >>= 1) ss += __shfl_down_sync(0xffffffffu, ss, o);
        nrm = sqrtf(ss);
    }
    __shared__ float wsum[8];
    if (lane == 0) wsum[threadIdx.x >> 5] = nrm;
    __syncthreads();
    if (threadIdx.x < 8) {
        float v = wsum[threadIdx.x];
#pragma unroll
        for (int o = 4; o > 0; o >>= 1) v += __shfl_down_sync(0xffu, v, o);
        if (threadIdx.x == 0) atomicAdd(&g_normsum, v);
    }
}

// ---------------- scale + segment pool --------------------------------------
__global__ void k_pool(float* __restrict__ out) {
    int b = blockIdx.x, g = threadIdx.x;
    float factor = 16.0f * (float)NN / g_normsum;   // sqrt(256)/mean(norm)
    const float* base = &g_h2[(size_t)b * NATOMS * DD + g];
    float s = 0.f;
#pragma unroll
    for (int a = 0; a < NATOMS; a++) s += base[a * DD];
    s *= factor;
    out[b * 512 + g] = s;                // mol_embedding[:, :256]
    out[BB * 512 + b * DD + g] = s;      // mol_atom_embedding
}

// ---------------- reaction: item/target embeddings --------------------------
__global__ void k_molemb(const int* __restrict__ idl, const int* __restrict__ idt,
                         const float* __restrict__ mfea, const float* __restrict__ femb)
{
    int b = blockIdx.x, g = threadIdx.x;
    __shared__ float sm[4][40];
    __shared__ int ids[4];
    if (g < 4) ids[g] = (g < 2) ? idl[g * BB + b] : idt[(g - 2) * BB + b];
    __syncthreads();
    if (g < 160) sm[g / 40][g % 40] = mfea[(size_t)ids[g / 40] * 40 + (g % 40)];
    __syncthreads();
    float e0 = 0, e1 = 0, e2 = 0, e3 = 0;
#pragma unroll
    for (int j = 0; j < 40; j++) {
        float f = femb[j * DD + g];
        e0 += sm[0][j] * f;
        e1 += sm[1][j] * f;
        e2 += sm[2][j] * f;
        e3 += sm[3][j] * f;
    }
    g_item[(0 * BB + b) * DD + g] = e0;
    g_item[(1 * BB + b) * DD + g] = e1;
    g_target[b * DD + g] = 0.5f * (e0 + e1) + 0.5f * (e2 + e3);
}

// ---------------- fused neighbor attention: both sides s=0,1 in one block ---
__global__ __launch_bounds__(256) void k_att2(
    const int* __restrict__ id_list, const int* __restrict__ neimat,
    const float* __restrict__ mfea, const float* __restrict__ femb,
    const float* __restrict__ attw, float* __restrict__ outp)
{
    int b = blockIdx.x;
    int g = threadIdx.x;
    int warp = g >> 5, lane = g & 31;

    __shared__ float nei[KNEI * DD];     // 32 KB
    __shared__ float mrow[KNEI * 40];    // 5 KB
    __shared__ float wv[DD];
    __shared__ float att[KNEI];
    __shared__ int nids[KNEI];

    float res = 0.f;
#pragma unroll
    for (int s = 0; s < SSIDE; s++) {
        __syncthreads();                 // smem reuse guard across s
        int id = id_list[s * BB + b];
        if (g < KNEI) nids[g] = neimat[id * KNEI + g];
        float itemv = g_item[(s * BB + b) * DD + g];
        wv[g] = itemv * g_target[b * DD + g] * attw[g];
        __syncthreads();
        for (int i = g; i < KNEI * 40; i += 256)
            mrow[i] = mfea[(size_t)nids[i / 40] * 40 + (i % 40)];
        __syncthreads();

        // nei[k][g] = sum_j mrow[k][j] * femb[j][g]
        for (int k = 0; k < KNEI; k++) {
            float acc = 0.f;
#pragma unroll
            for (int j = 0; j < 40; j++) acc += mrow[k * 40 + j] * femb[j * DD + g];
            nei[k * DD + g] = acc;
        }
        __syncthreads();

        // logits[k] = sum_g wv[g]*nei[k][g]  (att_b cancels in softmax)
#pragma unroll
        for (int kk = 0; kk < 4; kk++) {
            int k = warp * 4 + kk;
            float p = 0.f;
#pragma unroll
            for (int i = 0; i < 8; i++)
                p += wv[lane + i * 32] * nei[k * DD + lane + i * 32];
#pragma unroll
            for (int o = 16; o > 0; o >>= 1)
                p += __shfl_down_sync(0xffffffffu, p, o);
            if (lane == 0) att[k] = p;
        }
        __syncthreads();

        if (g < 32) {                    // softmax over 32 neighbors
            float x = att[g];
            float m = x;
#pragma unroll
            for (int o = 16; o > 0; o >>= 1)
                m = fmaxf(m, __shfl_xor_sync(0xffffffffu, m, o));
            float ex = expf(x - m);
            float su = ex;
#pragma unroll
            for (int o = 16; o > 0; o >>= 1)
                su += __shfl_xor_sync(0xffffffffu, su, o);
            att[g] = ex / su;
        }
        __syncthreads();

        float agg = 0.f;
#pragma unroll
        for (int k = 0; k < KNEI; k++) agg += att[k] * nei[k * DD + g];
        res += 0.5f * (itemv + agg);
    }

    g_react[b * DD + g] = res;           // input for crosscl GEMM
    outp[b * 512 + 256 + g] = res;       // mol_embedding[:, 256:]
}

// ---------------- launch ----------------------------------------------------
extern "C" void kernel_launch(void* const* d_in, const int* in_sizes, int n_in,
                              void* d_out, int out_size)
{
    const int*   node_feat = (const int*)d_in[0];
    const int*   edge_src  = (const int*)d_in[1];
    const int*   edge_dst  = (const int*)d_in[2];
    /* d_in[3] graph_ids: contiguous repeat(arange(B),30) -> implicit */
    const int*   id_list   = (const int*)d_in[4];
    const int*   id_tgt    = (const int*)d_in[5];
    const float* mfea      = (const float*)d_in[6];
    const int*   neimat    = (const int*)d_in[7];
    const float* W0        = (const float*)d_in[8];
    const float* b0        = (const float*)d_in[9];
    const float* W1        = (const float*)d_in[10];
    const float* b1        = (const float*)d_in[11];
    const float* femb      = (const float*)d_in[12];
    const float* attw      = (const float*)d_in[13];
    /* d_in[14] att_b cancels in softmax */
    const float* cw        = (const float*)d_in[15];
    const float* cb        = (const float*)d_in[16];
    float* out = (float*)d_out;

    float *p_agg1, *p_agg2, *p_react, *p_ndst;
    float *p_h1, *p_h2;
    cudaGetSymbolAddress((void**)&p_agg1,  g_agg1);
    cudaGetSymbolAddress((void**)&p_agg2,  g_agg2);
    cudaGetSymbolAddress((void**)&p_h1,    g_h1);
    cudaGetSymbolAddress((void**)&p_h2,    g_h2);
    cudaGetSymbolAddress((void**)&p_ndst,  g_norm_dst);
    cudaGetSymbolAddress((void**)&p_react, g_react);

    k_zero_all<<<NN * FL / 4 / 256, 256>>>();
    k_deg<<<EE / 256, 256>>>(edge_src, edge_dst);
    k_norm<<<NN / 256, 256>>>();
    k_scan<<<1, 1024>>>();
    k_place<<<EE / 256, 256>>>(edge_src, edge_dst);

    // --- atom GCN chain ---
    k_scatter1<<<EE / 256, 256>>>(edge_src, edge_dst, node_feat);
    {
        dim3 grid(NN / 128, 2);
        k_mgemm<<<grid, 256>>>(p_agg1, p_ndst, W0, b0, p_h1, FL, 1);
    }
    k_gather<<<NN * 64 / 256, 256>>>();
    {
        dim3 grid(NN / 128, 2);
        k_mgemm<<<grid, 256>>>(p_agg2, p_ndst, W1, b1, p_h2, DD, 0);
    }
    k_normreduce<<<NN * 32 / 256, 256>>>();
    k_pool<<<BB, 256>>>(out);

    // --- reaction / KG chain ---
    k_molemb<<<BB, 256>>>(id_list, id_tgt, mfea, femb);
    k_att2<<<BB, 256>>>(id_list, neimat, mfea, femb, attw, out);
    {
        dim3 grid(BB / 128, 2);
        k_mgemm<<<grid, 256>>>(p_react, nullptr, cw, cb,
                               out + BB * 512 + BB * DD, DD, 0);
    }
}

// round 11
// speedup vs baseline: 1.1258x; 1.1258x over previous
#include <cuda_runtime.h>
#include <cuda_bf16.h>
#include <cstdint>

#define NN      61440        // nodes = 2048*30
#define EE      245760       // edges = 4*NN
#define BB      2048         // graphs
#define NATOMS  30
#define FL      64           // FEATURE_LEN
#define DD      256          // DIM_ATOM == DIM_GRAPH
#define SSIDE   2            // S
#define KNEI    32
#define SLOTS   48           // padded neighbor slots per dst (deg~Pois(4))

// ---------------- device scratch (no runtime allocation allowed) ------------
__device__ float    g_norm_src[NN];
__device__ float    g_norm_dst[NN];
__device__ unsigned g_cnt[NN];            // in-degree / placement cursor
__device__ int      g_bins[NN * SLOTS];   // src ids binned by dst (padded)
__device__ float    g_agg1[NN * FL];
__device__ float    g_h1[NN * DD];
__device__ float    g_agg2[NN * DD];
__device__ float    g_h2[NN * DD];
__device__ float    g_item[SSIDE * BB * DD];
__device__ float    g_target[BB * DD];
__device__ float    g_react[BB * DD];
__device__ float    g_normsum;

// ---------------- zero accumulators (agg2 NOT zeroed: gather overwrites) ----
__global__ void k_zero_all() {
    int t = blockIdx.x * blockDim.x + threadIdx.x;   // 3840*256 = 983040
    float4 z = make_float4(0.f, 0.f, 0.f, 0.f);
    ((float4*)g_agg1)[t] = z;                         // NN*FL/4 = 983040 exactly
    if (t < NN / 4) {
        ((float4*)g_norm_src)[t] = z;
        ((uint4*)g_cnt)[t] = make_uint4(0u, 0u, 0u, 0u);
    }
    if (t == 0) g_normsum = 0.f;
}

// ---------------- one edge pass: out-degree + padded binning by dst ---------
__global__ void k_deg_place(const int* __restrict__ src, const int* __restrict__ dst) {
    int e = blockIdx.x * blockDim.x + threadIdx.x;
    if (e < EE) {
        int s = __ldg(&src[e]), d = __ldg(&dst[e]);
        atomicAdd(&g_norm_src[s], 1.0f);
        unsigned slot = atomicAdd(&g_cnt[d], 1u);
        if (slot >= SLOTS) slot = SLOTS - 1;          // theoretical-only clamp
        g_bins[(size_t)d * SLOTS + slot] = s;
    }
}

__global__ void k_norm() {
    int n = blockIdx.x * blockDim.x + threadIdx.x;
    if (n < NN) {
        g_norm_src[n] = rsqrtf(fmaxf(g_norm_src[n], 1.0f));
        g_norm_dst[n] = rsqrtf(fmaxf((float)g_cnt[n], 1.0f));
    }
}

// ---------------- layer-1 sparse scatter (one-hot messages) -----------------
__global__ void k_scatter1(const int* __restrict__ src, const int* __restrict__ dst,
                           const int* __restrict__ feat) {
    int e = blockIdx.x * blockDim.x + threadIdx.x;
    if (e < EE) {
        int s = __ldg(&src[e]), d = __ldg(&dst[e]);
        float ns = g_norm_src[s];
        float* ag = &g_agg1[d * FL];
        int4 f = *(const int4*)&feat[s * 4];
        atomicAdd(&ag[f.x], ns);
        atomicAdd(&ag[f.y], ns);
        atomicAdd(&ag[f.z], ns);
        atomicAdd(&ag[f.w], ns);
    }
}

// ---------------- layer-2 dense aggregation: padded-bin gather (no atomics) -
// 64 threads per dst row, float4 per thread; h1 rows stream through L2.
__global__ void k_gather() {
    int t = blockIdx.x * blockDim.x + threadIdx.x;
    int row = t >> 6;
    int c = (t & 63) * 4;
    unsigned n = g_cnt[row];
    if (n > SLOTS) n = SLOTS;
    const int* bin = &g_bins[(size_t)row * SLOTS];
    float4 acc = make_float4(0.f, 0.f, 0.f, 0.f);
    for (unsigned j = 0; j < n; j++) {
        int s = bin[j];                               // broadcast across group
        float ns = g_norm_src[s];
        float4 v = *(const float4*)&g_h1[(size_t)s * DD + c];
        acc.x += ns * v.x; acc.y += ns * v.y;
        acc.z += ns * v.z; acc.w += ns * v.w;
    }
    *(float4*)&g_agg2[(size_t)row * DD + c] = acc;
}

// ============================================================================
//  mma.sync bf16 3-split GEMM:  out[M,256] = (A*rowscale)[M,K] @ W[K,256] + b
// ============================================================================
#define SMS 36   // smem row stride in bf16 elements (32 + 4 pad)

__device__ __forceinline__ void mma16816(float* c, const uint32_t* a,
                                         const uint32_t* b) {
    asm volatile(
        "mma.sync.aligned.m16n8k16.row.col.f32.bf16.bf16.f32 "
        "{%0,%1,%2,%3}, {%4,%5,%6,%7}, {%8,%9}, {%0,%1,%2,%3};"
        : "+f"(c[0]), "+f"(c[1]), "+f"(c[2]), "+f"(c[3])
        : "r"(a[0]), "r"(a[1]), "r"(a[2]), "r"(a[3]), "r"(b[0]), "r"(b[1]));
}

__global__ __launch_bounds__(256) void k_mgemm(
    const float* __restrict__ A, const float* __restrict__ rowscale,
    const float* __restrict__ W, const float* __restrict__ bias,
    float* __restrict__ out, int K, int relu)
{
    __shared__ __nv_bfloat16 AsH[128 * SMS];
    __shared__ __nv_bfloat16 AsL[128 * SMS];
    __shared__ __nv_bfloat16 BsH[128 * SMS];
    __shared__ __nv_bfloat16 BsL[128 * SMS];

    int tid = threadIdx.x;
    int wid = tid >> 5, lane = tid & 31;
    int warpM = wid & 1, warpN = wid >> 1;     // 2 x 4 warp grid
    int g = lane >> 2, tg = lane & 3;          // mma group / thread-in-group
    int bm = blockIdx.x * 128;
    int bn = blockIdx.y * 128;

    float acc[4][4][4];
#pragma unroll
    for (int mi = 0; mi < 4; mi++)
#pragma unroll
        for (int ni = 0; ni < 4; ni++)
#pragma unroll
            for (int r = 0; r < 4; r++) acc[mi][ni][r] = 0.f;

    int arow = tid >> 1, ahalf = tid & 1;      // A loader: 128 rows x 2 halves
    float rsc = rowscale ? __ldg(&rowscale[bm + arow]) : 1.0f;
    int bk = tid >> 3, bn16 = (tid & 7) * 16;  // B loader: 32 k-rows x 8 n-grp

    for (int kc = 0; kc < K; kc += 32) {
        // ---- A chunk 128x32: split hi/lo ----
        {
            const float* ap = &A[(size_t)(bm + arow) * K + kc + ahalf * 16];
            int base = arow * SMS + ahalf * 16;
#pragma unroll
            for (int i = 0; i < 4; i++) {
                float4 v = *(const float4*)(ap + i * 4);
                v.x *= rsc; v.y *= rsc; v.z *= rsc; v.w *= rsc;
                __nv_bfloat16 hx = __float2bfloat16_rn(v.x);
                __nv_bfloat16 hy = __float2bfloat16_rn(v.y);
                __nv_bfloat16 hz = __float2bfloat16_rn(v.z);
                __nv_bfloat16 hw = __float2bfloat16_rn(v.w);
                __nv_bfloat162 hxy = __halves2bfloat162(hx, hy);
                __nv_bfloat162 hzw = __halves2bfloat162(hz, hw);
                __nv_bfloat162 lxy = __floats2bfloat162_rn(
                    v.x - __bfloat162float(hx), v.y - __bfloat162float(hy));
                __nv_bfloat162 lzw = __floats2bfloat162_rn(
                    v.z - __bfloat162float(hz), v.w - __bfloat162float(hw));
                *(__nv_bfloat162*)&AsH[base + i * 4]     = hxy;
                *(__nv_bfloat162*)&AsH[base + i * 4 + 2] = hzw;
                *(__nv_bfloat162*)&AsL[base + i * 4]     = lxy;
                *(__nv_bfloat162*)&AsL[base + i * 4 + 2] = lzw;
            }
        }
        // ---- B chunk 32x128 -> transposed Bs[n][k], split hi/lo ----
        {
            const float* wp = &W[(size_t)(kc + bk) * 256 + bn + bn16];
#pragma unroll
            for (int j4 = 0; j4 < 4; j4++) {
                float4 v = *(const float4*)(wp + j4 * 4);
                float vv[4] = {v.x, v.y, v.z, v.w};
#pragma unroll
                for (int e2 = 0; e2 < 4; e2++) {
                    int n = bn16 + j4 * 4 + e2;
                    __nv_bfloat16 h = __float2bfloat16_rn(vv[e2]);
                    BsH[n * SMS + bk] = h;
                    BsL[n * SMS + bk] = __float2bfloat16_rn(vv[e2] - __bfloat162float(h));
                }
            }
        }
        __syncthreads();

#pragma unroll
        for (int ks = 0; ks < 32; ks += 16) {
            uint32_t aH[4][4], aL[4][4], bH[4][2], bL[4][2];
#pragma unroll
            for (int mi = 0; mi < 4; mi++) {
                int r0 = (warpM * 64 + mi * 16 + g) * SMS + ks + tg * 2;
                int r1 = r0 + 8 * SMS;
                aH[mi][0] = *(const uint32_t*)&AsH[r0];
                aH[mi][1] = *(const uint32_t*)&AsH[r1];
                aH[mi][2] = *(const uint32_t*)&AsH[r0 + 8];
                aH[mi][3] = *(const uint32_t*)&AsH[r1 + 8];
                aL[mi][0] = *(const uint32_t*)&AsL[r0];
                aL[mi][1] = *(const uint32_t*)&AsL[r1];
                aL[mi][2] = *(const uint32_t*)&AsL[r0 + 8];
                aL[mi][3] = *(const uint32_t*)&AsL[r1 + 8];
            }
#pragma unroll
            for (int ni = 0; ni < 4; ni++) {
                int n0 = (warpN * 32 + ni * 8 + g) * SMS + ks + tg * 2;
                bH[ni][0] = *(const uint32_t*)&BsH[n0];
                bH[ni][1] = *(const uint32_t*)&BsH[n0 + 8];
                bL[ni][0] = *(const uint32_t*)&BsL[n0];
                bL[ni][1] = *(const uint32_t*)&BsL[n0 + 8];
            }
#pragma unroll
            for (int mi = 0; mi < 4; mi++)
#pragma unroll
                for (int ni = 0; ni < 4; ni++) {
                    mma16816(acc[mi][ni], aH[mi], bH[ni]);
                    mma16816(acc[mi][ni], aL[mi], bH[ni]);
                    mma16816(acc[mi][ni], aH[mi], bL[ni]);
                }
        }
        __syncthreads();
    }

    // ---- epilogue: bias (+relu), write fp32 ----
#pragma unroll
    for (int mi = 0; mi < 4; mi++) {
        int row0 = bm + warpM * 64 + mi * 16 + g;
#pragma unroll
        for (int ni = 0; ni < 4; ni++) {
            int col = bn + warpN * 32 + ni * 8 + tg * 2;
            float b0 = __ldg(&bias[col]), b1 = __ldg(&bias[col + 1]);
            float2 v0, v1;
            v0.x = acc[mi][ni][0] + b0; v0.y = acc[mi][ni][1] + b1;
            v1.x = acc[mi][ni][2] + b0; v1.y = acc[mi][ni][3] + b1;
            if (relu) {
                v0.x = fmaxf(v0.x, 0.f); v0.y = fmaxf(v0.y, 0.f);
                v1.x = fmaxf(v1.x, 0.f); v1.y = fmaxf(v1.y, 0.f);
            }
            *(float2*)&out[(size_t)row0 * 256 + col] = v0;
            *(float2*)&out[(size_t)(row0 + 8) * 256 + col] = v1;
        }
    }
}

// ---------------- mean row-norm of h2 ---------------------------------------
__global__ void k_normreduce() {
    int gwarp = (blockIdx.x * blockDim.x + threadIdx.x) >> 5;
    int lane = threadIdx.x & 31;
    float nrm = 0.f;
    {
        const float* row = &g_h2[(size_t)gwarp * DD];
        float ss = 0.f;
#pragma unroll
        for (int i = 0; i < 8; i++) {
            float v = row[lane + i * 32];
            ss += v * v;
        }
#pragma unroll
        for (int o = 16; o > 0; o >>= 1) ss += __shfl_down_sync(0xffffffffu, ss, o);
        nrm = sqrtf(ss);
    }
    __shared__ float wsum[8];
    if (lane == 0) wsum[threadIdx.x >> 5] = nrm;
    __syncthreads();
    if (threadIdx.x < 8) {
        float v = wsum[threadIdx.x];
#pragma unroll
        for (int o = 4; o > 0; o >>= 1) v += __shfl_down_sync(0xffu, v, o);
        if (threadIdx.x == 0) atomicAdd(&g_normsum, v);
    }
}

// ---------------- scale + segment pool --------------------------------------
__global__ void k_pool(float* __restrict__ out) {
    int b = blockIdx.x, g = threadIdx.x;
    float factor = 16.0f * (float)NN / g_normsum;   // sqrt(256)/mean(norm)
    const float* base = &g_h2[(size_t)b * NATOMS * DD + g];
    float s = 0.f;
#pragma unroll
    for (int a = 0; a < NATOMS; a++) s += base[a * DD];
    s *= factor;
    out[b * 512 + g] = s;                // mol_embedding[:, :256]
    out[BB * 512 + b * DD + g] = s;      // mol_atom_embedding
}

// ---------------- reaction: item/target embeddings --------------------------
__global__ void k_molemb(const int* __restrict__ idl, const int* __restrict__ idt,
                         const float* __restrict__ mfea, const float* __restrict__ femb)
{
    int b = blockIdx.x, g = threadIdx.x;
    __shared__ float sm[4][40];
    __shared__ int ids[4];
    if (g < 4) ids[g] = (g < 2) ? idl[g * BB + b] : idt[(g - 2) * BB + b];
    __syncthreads();
    if (g < 160) sm[g / 40][g % 40] = mfea[(size_t)ids[g / 40] * 40 + (g % 40)];
    __syncthreads();
    float e0 = 0, e1 = 0, e2 = 0, e3 = 0;
#pragma unroll
    for (int j = 0; j < 40; j++) {
        float f = femb[j * DD + g];
        e0 += sm[0][j] * f;
        e1 += sm[1][j] * f;
        e2 += sm[2][j] * f;
        e3 += sm[3][j] * f;
    }
    g_item[(0 * BB + b) * DD + g] = e0;
    g_item[(1 * BB + b) * DD + g] = e1;
    g_target[b * DD + g] = 0.5f * (e0 + e1) + 0.5f * (e2 + e3);
}

// ---------------- fused neighbor attention: both sides s=0,1 in one block ---
__global__ __launch_bounds__(256) void k_att2(
    const int* __restrict__ id_list, const int* __restrict__ neimat,
    const float* __restrict__ mfea, const float* __restrict__ femb,
    const float* __restrict__ attw, float* __restrict__ outp)
{
    int b = blockIdx.x;
    int g = threadIdx.x;
    int warp = g >> 5, lane = g & 31;

    __shared__ float nei[KNEI * DD];     // 32 KB
    __shared__ float mrow[KNEI * 40];    // 5 KB
    __shared__ float wv[DD];
    __shared__ float att[KNEI];
    __shared__ int nids[KNEI];

    float res = 0.f;
#pragma unroll
    for (int s = 0; s < SSIDE; s++) {
        __syncthreads();                 // smem reuse guard across s
        int id = id_list[s * BB + b];
        if (g < KNEI) nids[g] = neimat[id * KNEI + g];
        float itemv = g_item[(s * BB + b) * DD + g];
        wv[g] = itemv * g_target[b * DD + g] * attw[g];
        __syncthreads();
        for (int i = g; i < KNEI * 40; i += 256)
            mrow[i] = mfea[(size_t)nids[i / 40] * 40 + (i % 40)];
        __syncthreads();

        // nei[k][g] = sum_j mrow[k][j] * femb[j][g]
        for (int k = 0; k < KNEI; k++) {
            float acc = 0.f;
#pragma unroll
            for (int j = 0; j < 40; j++) acc += mrow[k * 40 + j] * femb[j * DD + g];
            nei[k * DD + g] = acc;
        }
        __syncthreads();

        // logits[k] = sum_g wv[g]*nei[k][g]  (att_b cancels in softmax)
#pragma unroll
        for (int kk = 0; kk < 4; kk++) {
            int k = warp * 4 + kk;
            float p = 0.f;
#pragma unroll
            for (int i = 0; i < 8; i++)
                p += wv[lane + i * 32] * nei[k * DD + lane + i * 32];
#pragma unroll
            for (int o = 16; o > 0; o >>= 1)
                p += __shfl_down_sync(0xffffffffu, p, o);
            if (lane == 0) att[k] = p;
        }
        __syncthreads();

        if (g < 32) {                    // softmax over 32 neighbors
            float x = att[g];
            float m = x;
#pragma unroll
            for (int o = 16; o > 0; o >>= 1)
                m = fmaxf(m, __shfl_xor_sync(0xffffffffu, m, o));
            float ex = expf(x - m);
            float su = ex;
#pragma unroll
            for (int o = 16; o > 0; o >>= 1)
                su += __shfl_xor_sync(0xffffffffu, su, o);
            att[g] = ex / su;
        }
        __syncthreads();

        float agg = 0.f;
#pragma unroll
        for (int k = 0; k < KNEI; k++) agg += att[k] * nei[k * DD + g];
        res += 0.5f * (itemv + agg);
    }

    g_react[b * DD + g] = res;           // input for crosscl GEMM
    outp[b * 512 + 256 + g] = res;       // mol_embedding[:, 256:]
}

// ---------------- launch ----------------------------------------------------
extern "C" void kernel_launch(void* const* d_in, const int* in_sizes, int n_in,
                              void* d_out, int out_size)
{
    const int*   node_feat = (const int*)d_in[0];
    const int*   edge_src  = (const int*)d_in[1];
    const int*   edge_dst  = (const int*)d_in[2];
    /* d_in[3] graph_ids: contiguous repeat(arange(B),30) -> implicit */
    const int*   id_list   = (const int*)d_in[4];
    const int*   id_tgt    = (const int*)d_in[5];
    const float* mfea      = (const float*)d_in[6];
    const int*   neimat    = (const int*)d_in[7];
    const float* W0        = (const float*)d_in[8];
    const float* b0        = (const float*)d_in[9];
    const float* W1        = (const float*)d_in[10];
    const float* b1        = (const float*)d_in[11];
    const float* femb      = (const float*)d_in[12];
    const float* attw      = (const float*)d_in[13];
    /* d_in[14] att_b cancels in softmax */
    const float* cw        = (const float*)d_in[15];
    const float* cb        = (const float*)d_in[16];
    float* out = (float*)d_out;

    float *p_agg1, *p_agg2, *p_react, *p_ndst;
    float *p_h1, *p_h2;
    cudaGetSymbolAddress((void**)&p_agg1,  g_agg1);
    cudaGetSymbolAddress((void**)&p_agg2,  g_agg2);
    cudaGetSymbolAddress((void**)&p_h1,    g_h1);
    cudaGetSymbolAddress((void**)&p_h2,    g_h2);
    cudaGetSymbolAddress((void**)&p_ndst,  g_norm_dst);
    cudaGetSymbolAddress((void**)&p_react, g_react);

    k_zero_all<<<NN * FL / 4 / 256, 256>>>();
    k_deg_place<<<EE / 256, 256>>>(edge_src, edge_dst);
    k_norm<<<NN / 256, 256>>>();

    // --- atom GCN chain ---
    k_scatter1<<<EE / 256, 256>>>(edge_src, edge_dst, node_feat);
    {
        dim3 grid(NN / 128, 2);
        k_mgemm<<<grid, 256>>>(p_agg1, p_ndst, W0, b0, p_h1, FL, 1);
    }
    k_gather<<<NN * 64 / 256, 256>>>();
    {
        dim3 grid(NN / 128, 2);
        k_mgemm<<<grid, 256>>>(p_agg2, p_ndst, W1, b1, p_h2, DD, 0);
    }
    k_normreduce<<<NN * 32 / 256, 256>>>();
    k_pool<<<BB, 256>>>(out);

    // --- reaction / KG chain ---
    k_molemb<<<BB, 256>>>(id_list, id_tgt, mfea, femb);
    k_att2<<<BB, 256>>>(id_list, neimat, mfea, femb, attw, out);
    {
        dim3 grid(BB / 128, 2);
        k_mgemm<<<grid, 256>>>(p_react, nullptr, cw, cb,
                               out + BB * 512 + BB * DD, DD, 0);
    }
}

// round 12
// speedup vs baseline: 1.2443x; 1.1053x over previous
#include <cuda_runtime.h>
#include <cuda_bf16.h>
#include <cstdint>

#define NN      61440        // nodes = 2048*30
#define EE      245760       // edges = 4*NN
#define BB      2048         // graphs
#define NATOMS  30
#define FL      64           // FEATURE_LEN
#define DD      256          // DIM_ATOM == DIM_GRAPH
#define SSIDE   2            // S
#define KNEI    32
#define SLOTS   48           // padded neighbor slots per dst (deg~Pois(4))

// ---------------- device scratch (no runtime allocation allowed) ------------
__device__ float    g_degs[NN];           // out-degree (float counts)
__device__ unsigned g_cnt[NN];            // in-degree / placement cursor
__device__ int      g_bins[NN * SLOTS];   // src ids binned by dst (padded)
__device__ float    g_agg1[NN * FL];
__device__ float    g_h1[NN * DD];
__device__ float    g_agg2[NN * DD];
__device__ float    g_h2[NN * DD];
__device__ float    g_item[SSIDE * BB * DD];
__device__ float    g_target[BB * DD];
__device__ float    g_react[BB * DD];
__device__ float    g_normsum;

// ---------------- zero accumulators (agg2 NOT zeroed: gather overwrites) ----
__global__ void k_zero_all() {
    int t = blockIdx.x * blockDim.x + threadIdx.x;   // 3840*256 = 983040
    float4 z = make_float4(0.f, 0.f, 0.f, 0.f);
    ((float4*)g_agg1)[t] = z;                         // NN*FL/4 = 983040 exactly
    if (t < NN / 4) {
        ((float4*)g_degs)[t] = z;
        ((uint4*)g_cnt)[t] = make_uint4(0u, 0u, 0u, 0u);
    }
    if (t == 0) g_normsum = 0.f;
}

// ---------------- one edge pass: out-degree + padded binning by dst ---------
__global__ void k_deg_place(const int* __restrict__ src, const int* __restrict__ dst) {
    int e = blockIdx.x * blockDim.x + threadIdx.x;
    if (e < EE) {
        int s = __ldg(&src[e]), d = __ldg(&dst[e]);
        atomicAdd(&g_degs[s], 1.0f);
        unsigned slot = atomicAdd(&g_cnt[d], 1u);
        if (slot >= SLOTS) slot = SLOTS - 1;          // theoretical-only clamp
        g_bins[(size_t)d * SLOTS + slot] = s;
    }
}

// ---------------- layer-1 sparse scatter (one-hot; rsqrt inline) ------------
__global__ void k_scatter1(const int* __restrict__ src, const int* __restrict__ dst,
                           const int* __restrict__ feat) {
    int e = blockIdx.x * blockDim.x + threadIdx.x;
    if (e < EE) {
        int s = __ldg(&src[e]), d = __ldg(&dst[e]);
        float ns = rsqrtf(fmaxf(g_degs[s], 1.0f));
        float* ag = &g_agg1[d * FL];
        int4 f = *(const int4*)&feat[s * 4];
        atomicAdd(&ag[f.x], ns);
        atomicAdd(&ag[f.y], ns);
        atomicAdd(&ag[f.z], ns);
        atomicAdd(&ag[f.w], ns);
    }
}

// ---------------- layer-2 dense aggregation: padded-bin gather (no atomics) -
__global__ void k_gather() {
    int t = blockIdx.x * blockDim.x + threadIdx.x;
    int row = t >> 6;
    int c = (t & 63) * 4;
    unsigned n = g_cnt[row];
    if (n > SLOTS) n = SLOTS;
    const int* bin = &g_bins[(size_t)row * SLOTS];
    float4 acc = make_float4(0.f, 0.f, 0.f, 0.f);
    for (unsigned j = 0; j < n; j++) {
        int s = bin[j];                               // broadcast across group
        float ns = rsqrtf(fmaxf(g_degs[s], 1.0f));
        float4 v = *(const float4*)&g_h1[(size_t)s * DD + c];
        acc.x += ns * v.x; acc.y += ns * v.y;
        acc.z += ns * v.z; acc.w += ns * v.w;
    }
    *(float4*)&g_agg2[(size_t)row * DD + c] = acc;
}

// ============================================================================
//  mma.sync bf16 3-split GEMM:  out[M,256] = (A*rsqrt(cnt))[M,K] @ W[K,256]+b
//  rowscale: in-degree counts (unsigned) or nullptr.
// ============================================================================
#define SMS 36   // smem row stride in bf16 elements (32 + 4 pad)

__device__ __forceinline__ void mma16816(float* c, const uint32_t* a,
                                         const uint32_t* b) {
    asm volatile(
        "mma.sync.aligned.m16n8k16.row.col.f32.bf16.bf16.f32 "
        "{%0,%1,%2,%3}, {%4,%5,%6,%7}, {%8,%9}, {%0,%1,%2,%3};"
        : "+f"(c[0]), "+f"(c[1]), "+f"(c[2]), "+f"(c[3])
        : "r"(a[0]), "r"(a[1]), "r"(a[2]), "r"(a[3]), "r"(b[0]), "r"(b[1]));
}

__global__ __launch_bounds__(256) void k_mgemm(
    const float* __restrict__ A, const unsigned* __restrict__ rowcnt,
    const float* __restrict__ W, const float* __restrict__ bias,
    float* __restrict__ out, int K, int relu)
{
    __shared__ __nv_bfloat16 AsH[128 * SMS];
    __shared__ __nv_bfloat16 AsL[128 * SMS];
    __shared__ __nv_bfloat16 BsH[128 * SMS];
    __shared__ __nv_bfloat16 BsL[128 * SMS];

    int tid = threadIdx.x;
    int wid = tid >> 5, lane = tid & 31;
    int warpM = wid & 1, warpN = wid >> 1;     // 2 x 4 warp grid
    int g = lane >> 2, tg = lane & 3;          // mma group / thread-in-group
    int bm = blockIdx.x * 128;
    int bn = blockIdx.y * 128;

    float acc[4][4][4];
#pragma unroll
    for (int mi = 0; mi < 4; mi++)
#pragma unroll
        for (int ni = 0; ni < 4; ni++)
#pragma unroll
            for (int r = 0; r < 4; r++) acc[mi][ni][r] = 0.f;

    int arow = tid >> 1, ahalf = tid & 1;      // A loader: 128 rows x 2 halves
    float rsc = rowcnt ? rsqrtf(fmaxf((float)__ldg(&rowcnt[bm + arow]), 1.0f))
                       : 1.0f;
    int bkp = tid >> 4;                        // B loader: k-pair 0..15
    int bn8 = (tid & 15) * 8;                  //           8 n-values

    for (int kc = 0; kc < K; kc += 32) {
        // ---- A chunk 128x32: split hi/lo ----
        {
            const float* ap = &A[(size_t)(bm + arow) * K + kc + ahalf * 16];
            int base = arow * SMS + ahalf * 16;
#pragma unroll
            for (int i = 0; i < 4; i++) {
                float4 v = *(const float4*)(ap + i * 4);
                v.x *= rsc; v.y *= rsc; v.z *= rsc; v.w *= rsc;
                __nv_bfloat16 hx = __float2bfloat16_rn(v.x);
                __nv_bfloat16 hy = __float2bfloat16_rn(v.y);
                __nv_bfloat16 hz = __float2bfloat16_rn(v.z);
                __nv_bfloat16 hw = __float2bfloat16_rn(v.w);
                __nv_bfloat162 hxy = __halves2bfloat162(hx, hy);
                __nv_bfloat162 hzw = __halves2bfloat162(hz, hw);
                __nv_bfloat162 lxy = __floats2bfloat162_rn(
                    v.x - __bfloat162float(hx), v.y - __bfloat162float(hy));
                __nv_bfloat162 lzw = __floats2bfloat162_rn(
                    v.z - __bfloat162float(hz), v.w - __bfloat162float(hw));
                *(__nv_bfloat162*)&AsH[base + i * 4]     = hxy;
                *(__nv_bfloat162*)&AsH[base + i * 4 + 2] = hzw;
                *(__nv_bfloat162*)&AsL[base + i * 4]     = lxy;
                *(__nv_bfloat162*)&AsL[base + i * 4 + 2] = lzw;
            }
        }
        // ---- B chunk 32x128 -> Bs[n][k], k-pairs packed as bf16x2 STS.32 ---
        {
            const float* wp = &W[(size_t)(kc + 2 * bkp) * 256 + bn + bn8];
            float w0[8], w1[8];
            *(float4*)&w0[0] = *(const float4*)wp;
            *(float4*)&w0[4] = *(const float4*)(wp + 4);
            *(float4*)&w1[0] = *(const float4*)(wp + 256);
            *(float4*)&w1[4] = *(const float4*)(wp + 260);
#pragma unroll
            for (int j = 0; j < 8; j++) {
                int n = bn8 + j;
                __nv_bfloat16 h0 = __float2bfloat16_rn(w0[j]);
                __nv_bfloat16 h1 = __float2bfloat16_rn(w1[j]);
                __nv_bfloat162 hp = __halves2bfloat162(h0, h1);
                __nv_bfloat162 lp = __floats2bfloat162_rn(
                    w0[j] - __bfloat162float(h0), w1[j] - __bfloat162float(h1));
                *(__nv_bfloat162*)&BsH[n * SMS + 2 * bkp] = hp;
                *(__nv_bfloat162*)&BsL[n * SMS + 2 * bkp] = lp;
            }
        }
        __syncthreads();

#pragma unroll
        for (int ks = 0; ks < 32; ks += 16) {
            uint32_t aH[4][4], aL[4][4], bH[4][2], bL[4][2];
#pragma unroll
            for (int mi = 0; mi < 4; mi++) {
                int r0 = (warpM * 64 + mi * 16 + g) * SMS + ks + tg * 2;
                int r1 = r0 + 8 * SMS;
                aH[mi][0] = *(const uint32_t*)&AsH[r0];
                aH[mi][1] = *(const uint32_t*)&AsH[r1];
                aH[mi][2] = *(const uint32_t*)&AsH[r0 + 8];
                aH[mi][3] = *(const uint32_t*)&AsH[r1 + 8];
                aL[mi][0] = *(const uint32_t*)&AsL[r0];
                aL[mi][1] = *(const uint32_t*)&AsL[r1];
                aL[mi][2] = *(const uint32_t*)&AsL[r0 + 8];
                aL[mi][3] = *(const uint32_t*)&AsL[r1 + 8];
            }
#pragma unroll
            for (int ni = 0; ni < 4; ni++) {
                int n0 = (warpN * 32 + ni * 8 + g) * SMS + ks + tg * 2;
                bH[ni][0] = *(const uint32_t*)&BsH[n0];
                bH[ni][1] = *(const uint32_t*)&BsH[n0 + 8];
                bL[ni][0] = *(const uint32_t*)&BsL[n0];
                bL[ni][1] = *(const uint32_t*)&BsL[n0 + 8];
            }
#pragma unroll
            for (int mi = 0; mi < 4; mi++)
#pragma unroll
                for (int ni = 0; ni < 4; ni++) {
                    mma16816(acc[mi][ni], aH[mi], bH[ni]);
                    mma16816(acc[mi][ni], aL[mi], bH[ni]);
                    mma16816(acc[mi][ni], aH[mi], bL[ni]);
                }
        }
        __syncthreads();
    }

    // ---- epilogue: bias (+relu), write fp32 ----
#pragma unroll
    for (int mi = 0; mi < 4; mi++) {
        int row0 = bm + warpM * 64 + mi * 16 + g;
#pragma unroll
        for (int ni = 0; ni < 4; ni++) {
            int col = bn + warpN * 32 + ni * 8 + tg * 2;
            float b0 = __ldg(&bias[col]), b1 = __ldg(&bias[col + 1]);
            float2 v0, v1;
            v0.x = acc[mi][ni][0] + b0; v0.y = acc[mi][ni][1] + b1;
            v1.x = acc[mi][ni][2] + b0; v1.y = acc[mi][ni][3] + b1;
            if (relu) {
                v0.x = fmaxf(v0.x, 0.f); v0.y = fmaxf(v0.y, 0.f);
                v1.x = fmaxf(v1.x, 0.f); v1.y = fmaxf(v1.y, 0.f);
            }
            *(float2*)&out[(size_t)row0 * 256 + col] = v0;
            *(float2*)&out[(size_t)(row0 + 8) * 256 + col] = v1;
        }
    }
}

// ---------------- mean row-norm of h2 ---------------------------------------
__global__ void k_normreduce() {
    int gwarp = (blockIdx.x * blockDim.x + threadIdx.x) >> 5;
    int lane = threadIdx.x & 31;
    float nrm = 0.f;
    {
        const float* row = &g_h2[(size_t)gwarp * DD];
        float ss = 0.f;
#pragma unroll
        for (int i = 0; i < 8; i++) {
            float v = row[lane + i * 32];
            ss += v * v;
        }
#pragma unroll
        for (int o = 16; o > 0; o >>= 1) ss += __shfl_down_sync(0xffffffffu, ss, o);
        nrm = sqrtf(ss);
    }
    __shared__ float wsum[8];
    if (lane == 0) wsum[threadIdx.x >> 5] = nrm;
    __syncthreads();
    if (threadIdx.x < 8) {
        float v = wsum[threadIdx.x];
#pragma unroll
        for (int o = 4; o > 0; o >>= 1) v += __shfl_down_sync(0xffu, v, o);
        if (threadIdx.x == 0) atomicAdd(&g_normsum, v);
    }
}

// ---------------- scale + segment pool --------------------------------------
__global__ void k_pool(float* __restrict__ out) {
    int b = blockIdx.x, g = threadIdx.x;
    float factor = 16.0f * (float)NN / g_normsum;   // sqrt(256)/mean(norm)
    const float* base = &g_h2[(size_t)b * NATOMS * DD + g];
    float s = 0.f;
#pragma unroll
    for (int a = 0; a < NATOMS; a++) s += base[a * DD];
    s *= factor;
    out[b * 512 + g] = s;                // mol_embedding[:, :256]
    out[BB * 512 + b * DD + g] = s;      // mol_atom_embedding
}

// ---------------- reaction: item/target embeddings --------------------------
__global__ void k_molemb(const int* __restrict__ idl, const int* __restrict__ idt,
                         const float* __restrict__ mfea, const float* __restrict__ femb)
{
    int b = blockIdx.x, g = threadIdx.x;
    __shared__ float sm[4][40];
    __shared__ int ids[4];
    if (g < 4) ids[g] = (g < 2) ? idl[g * BB + b] : idt[(g - 2) * BB + b];
    __syncthreads();
    if (g < 160) sm[g / 40][g % 40] = mfea[(size_t)ids[g / 40] * 40 + (g % 40)];
    __syncthreads();
    float e0 = 0, e1 = 0, e2 = 0, e3 = 0;
#pragma unroll
    for (int j = 0; j < 40; j++) {
        float f = femb[j * DD + g];
        e0 += sm[0][j] * f;
        e1 += sm[1][j] * f;
        e2 += sm[2][j] * f;
        e3 += sm[3][j] * f;
    }
    g_item[(0 * BB + b) * DD + g] = e0;
    g_item[(1 * BB + b) * DD + g] = e1;
    g_target[b * DD + g] = 0.5f * (e0 + e1) + 0.5f * (e2 + e3);
}

// ---------------- fused neighbor attention: both sides s=0,1 in one block ---
__global__ __launch_bounds__(256) void k_att2(
    const int* __restrict__ id_list, const int* __restrict__ neimat,
    const float* __restrict__ mfea, const float* __restrict__ femb,
    const float* __restrict__ attw, float* __restrict__ outp)
{
    int b = blockIdx.x;
    int g = threadIdx.x;
    int warp = g >> 5, lane = g & 31;

    __shared__ float nei[KNEI * DD];     // 32 KB
    __shared__ float mrow[KNEI * 40];    // 5 KB
    __shared__ float wv[DD];
    __shared__ float att[KNEI];
    __shared__ int nids[KNEI];

    float res = 0.f;
#pragma unroll
    for (int s = 0; s < SSIDE; s++) {
        __syncthreads();                 // smem reuse guard across s
        int id = id_list[s * BB + b];
        if (g < KNEI) nids[g] = neimat[id * KNEI + g];
        float itemv = g_item[(s * BB + b) * DD + g];
        wv[g] = itemv * g_target[b * DD + g] * attw[g];
        __syncthreads();
        for (int i = g; i < KNEI * 40; i += 256)
            mrow[i] = mfea[(size_t)nids[i / 40] * 40 + (i % 40)];
        __syncthreads();

        // nei[k][g] = sum_j mrow[k][j] * femb[j][g]
        for (int k = 0; k < KNEI; k++) {
            float acc = 0.f;
#pragma unroll
            for (int j = 0; j < 40; j++) acc += mrow[k * 40 + j] * femb[j * DD + g];
            nei[k * DD + g] = acc;
        }
        __syncthreads();

        // logits[k] = sum_g wv[g]*nei[k][g]  (att_b cancels in softmax)
#pragma unroll
        for (int kk = 0; kk < 4; kk++) {
            int k = warp * 4 + kk;
            float p = 0.f;
#pragma unroll
            for (int i = 0; i < 8; i++)
                p += wv[lane + i * 32] * nei[k * DD + lane + i * 32];
#pragma unroll
            for (int o = 16; o > 0; o >>= 1)
                p += __shfl_down_sync(0xffffffffu, p, o);
            if (lane == 0) att[k] = p;
        }
        __syncthreads();

        if (g < 32) {                    // softmax over 32 neighbors
            float x = att[g];
            float m = x;
#pragma unroll
            for (int o = 16; o > 0; o >>= 1)
                m = fmaxf(m, __shfl_xor_sync(0xffffffffu, m, o));
            float ex = expf(x - m);
            float su = ex;
#pragma unroll
            for (int o = 16; o > 0; o >>= 1)
                su += __shfl_xor_sync(0xffffffffu, su, o);
            att[g] = ex / su;
        }
        __syncthreads();

        float agg = 0.f;
#pragma unroll
        for (int k = 0; k < KNEI; k++) agg += att[k] * nei[k * DD + g];
        res += 0.5f * (itemv + agg);
    }

    g_react[b * DD + g] = res;           // input for crosscl GEMM
    outp[b * 512 + 256 + g] = res;       // mol_embedding[:, 256:]
}

// ---------------- launch ----------------------------------------------------
extern "C" void kernel_launch(void* const* d_in, const int* in_sizes, int n_in,
                              void* d_out, int out_size)
{
    const int*   node_feat = (const int*)d_in[0];
    const int*   edge_src  = (const int*)d_in[1];
    const int*   edge_dst  = (const int*)d_in[2];
    /* d_in[3] graph_ids: contiguous repeat(arange(B),30) -> implicit */
    const int*   id_list   = (const int*)d_in[4];
    const int*   id_tgt    = (const int*)d_in[5];
    const float* mfea      = (const float*)d_in[6];
    const int*   neimat    = (const int*)d_in[7];
    const float* W0        = (const float*)d_in[8];
    const float* b0        = (const float*)d_in[9];
    const float* W1        = (const float*)d_in[10];
    const float* b1        = (const float*)d_in[11];
    const float* femb      = (const float*)d_in[12];
    const float* attw      = (const float*)d_in[13];
    /* d_in[14] att_b cancels in softmax */
    const float* cw        = (const float*)d_in[15];
    const float* cb        = (const float*)d_in[16];
    float* out = (float*)d_out;

    float *p_agg1, *p_agg2, *p_react, *p_h1, *p_h2;
    unsigned* p_cnt;
    cudaGetSymbolAddress((void**)&p_agg1,  g_agg1);
    cudaGetSymbolAddress((void**)&p_agg2,  g_agg2);
    cudaGetSymbolAddress((void**)&p_h1,    g_h1);
    cudaGetSymbolAddress((void**)&p_h2,    g_h2);
    cudaGetSymbolAddress((void**)&p_cnt,   g_cnt);
    cudaGetSymbolAddress((void**)&p_react, g_react);

    k_zero_all<<<NN * FL / 4 / 256, 256>>>();
    k_deg_place<<<EE / 256, 256>>>(edge_src, edge_dst);

    // --- atom GCN chain (launch #3 = scatter1, #4 = gemm1 -> ncu capture) ---
    k_scatter1<<<EE / 256, 256>>>(edge_src, edge_dst, node_feat);
    {
        dim3 grid(NN / 128, 2);
        k_mgemm<<<grid, 256>>>(p_agg1, p_cnt, W0, b0, p_h1, FL, 1);
    }
    k_gather<<<NN * 64 / 256, 256>>>();
    {
        dim3 grid(NN / 128, 2);
        k_mgemm<<<grid, 256>>>(p_agg2, p_cnt, W1, b1, p_h2, DD, 0);
    }
    k_normreduce<<<NN * 32 / 256, 256>>>();
    k_pool<<<BB, 256>>>(out);

    // --- reaction / KG chain ---
    k_molemb<<<BB, 256>>>(id_list, id_tgt, mfea, femb);
    k_att2<<<BB, 256>>>(id_list, neimat, mfea, femb, attw, out);
    {
        dim3 grid(BB / 128, 2);
        k_mgemm<<<grid, 256>>>(p_react, nullptr, cw, cb,
                               out + BB * 512 + BB * DD, DD, 0);
    }
}